// round 14
// baseline (speedup 1.0000x reference)
#include <cuda_runtime.h>
#include <cstdint>

#define NN 100000
#define EE 1600000
#define GG 1000
#define FIN 27
#define HID 128
#define LL 4
#define CFUSE 160   /* 64 bases + 96 comb */
#define EPSB 1e-5f

// ---------------- scratch (device globals; no runtime allocation) ----------------
__device__ float    g_h  [NN * HID];
__device__ float    g_tmp[NN * HID];
__device__ float    g_bs [NN * 64];            // bases (gather target, L2-resident)
__device__ float    g_cb [NN * 96];            // comb coefficients
__device__ unsigned g_Wt [LL * HID * CFUSE];   // tf32-converted fused weights
__device__ float    g_bfL[LL * CFUSE];
__device__ int      g_csr[EE];
__device__ int      g_off[NN + 1];
__device__ int      g_cur[NN];
__device__ int      g_dcnt[NN];
__device__ int      g_bi [NN];
__device__ float    g_degf[NN];
__device__ float    g_ps [256 * HID];          // block partials (MLP) / totals (main path)
__device__ float    g_pq [256 * HID];
__device__ float    g_aff[2 * HID];
__device__ float    g_pool[GG * HID];
__device__ float    g_m1 [GG * 64];
__device__ float    g_m2 [GG * 32];
__device__ int      g_is64;

// ---------------- dtype detection ----------------
__global__ void detect_kernel(const unsigned* __restrict__ raw) {
    __shared__ int nz;
    if (threadIdx.x == 0) nz = 0;
    __syncthreads();
    int local = 0;
    for (int i = threadIdx.x; i < 2048; i += blockDim.x)
        if (raw[2 * i + 1] != 0u) local++;
    if (local) atomicAdd(&nz, local);
    __syncthreads();
    if (threadIdx.x == 0) g_is64 = (nz == 0) ? 1 : 0;
}

// batch convert + counter zeroing in one pass
__global__ void prep_kernel(const void* __restrict__ raw) {
    int n = blockIdx.x * blockDim.x + threadIdx.x;
    if (n >= NN) return;
    if (g_is64) g_bi[n] = (int)((const long long*)raw)[n];
    else        g_bi[n] = ((const int*)raw)[n];
    g_dcnt[n] = 0;
    g_cur[n]  = 0;
}

// ---------------- CSR build (reads raw edge buffer directly) ----------------
__global__ void count_deg_kernel(const void* __restrict__ raw) {
    int e = blockIdx.x * blockDim.x + threadIdx.x;
    if (e >= EE) return;
    int d = g_is64 ? (int)((const long long*)raw)[(size_t)EE + e]
                   : ((const int*)raw)[EE + e];
    atomicAdd(&g_dcnt[d], 1);
}

__global__ void scan_kernel() {   // single block, 1024 threads; also writes g_degf
    __shared__ int wsum[32];
    __shared__ int carry_sh;
    int tid = threadIdx.x, lane = tid & 31, wid = tid >> 5;
    if (tid == 0) { carry_sh = 0; g_off[0] = 0; }
    __syncthreads();
    for (int base = 0; base < NN; base += 1024) {
        int i = base + tid;
        int v = (i < NN) ? g_dcnt[i] : 0;
        if (i < NN) g_degf[i] = (float)(v + 1);   // +1 self loop
        int x = v;
        #pragma unroll
        for (int s = 1; s < 32; s <<= 1) {
            int t = __shfl_up_sync(0xffffffffu, x, s);
            if (lane >= s) x += t;
        }
        if (lane == 31) wsum[wid] = x;
        __syncthreads();
        if (wid == 0) {
            int y = wsum[lane];
            #pragma unroll
            for (int s = 1; s < 32; s <<= 1) {
                int t = __shfl_up_sync(0xffffffffu, y, s);
                if (lane >= s) y += t;
            }
            wsum[lane] = y;
        }
        __syncthreads();
        int incl = x + (wid > 0 ? wsum[wid - 1] : 0) + carry_sh;
        if (i < NN) g_off[i + 1] = incl;
        __syncthreads();
        if (tid == 1023) carry_sh = incl;
        __syncthreads();
    }
}

__global__ void scatter_kernel(const void* __restrict__ raw) {
    int e = blockIdx.x * blockDim.x + threadIdx.x;
    if (e >= EE) return;
    int s, d;
    if (g_is64) {
        const long long* p = (const long long*)raw;
        s = (int)p[e]; d = (int)p[(size_t)EE + e];
    } else {
        const int* p = (const int*)raw;
        s = p[e]; d = p[EE + e];
    }
    int pos = g_off[d] + atomicAdd(&g_cur[d], 1);
    g_csr[pos] = s;
}

// ---------------- lin1: x[N,27] @ W[27,128] + b, fused BN stats ----------------
__global__ __launch_bounds__(128) void lin1_kernel(const float* __restrict__ x,
                                                   const float* __restrict__ W,
                                                   const float* __restrict__ b,
                                                   float* __restrict__ out) {
    __shared__ float Wsh[FIN * HID];
    __shared__ float xsh[16 * FIN];
    int t = threadIdx.x;
    for (int q = t; q < FIN * HID; q += 128) Wsh[q] = W[q];
    int row0 = blockIdx.x * 16;
    for (int q = t; q < 16 * FIN; q += 128) {
        int r = q / FIN, c = q % FIN;
        xsh[q] = x[(row0 + r) * FIN + c];        // NN % 16 == 0
    }
    __syncthreads();
    float bias = b[t];
    float sacc = 0.f, qacc = 0.f;
    #pragma unroll 4
    for (int i = 0; i < 16; i++) {
        float acc = bias;
        #pragma unroll
        for (int k = 0; k < FIN; k++)
            acc = fmaf(xsh[i * FIN + k], Wsh[k * HID + t], acc);
        out[(size_t)(row0 + i) * HID + t] = acc;
        sacc += acc; qacc = fmaf(acc, acc, qacc);
    }
    atomicAdd(&g_ps[t], sacc);
    atomicAdd(&g_pq[t], qacc);
}

// ---------------- pack fused weight (all layers, tf32) + zero stat totals ----------------
__global__ void pack_all_w_kernel(const float* __restrict__ bw, const float* __restrict__ cw,
                                  const float* __restrict__ cb) {
    int idx = blockIdx.x * blockDim.x + threadIdx.x;
    if (blockIdx.x == 0 && threadIdx.x < HID) {
        g_ps[threadIdx.x] = 0.f;
        g_pq[threadIdx.x] = 0.f;
    }
    if (idx < LL * HID * CFUSE) {
        int l = idx / (HID * CFUSE);
        int rem = idx % (HID * CFUSE);
        int k = rem / CFUSE, c = rem % CFUSE;
        float v = (c < 64) ? bw[(size_t)l * HID * 64 + k * 64 + c]
                           : cw[(size_t)l * HID * 96 + k * 96 + (c - 64)];
        unsigned u;
        asm("cvt.rna.tf32.f32 %0, %1;" : "=r"(u) : "f"(v));
        g_Wt[idx] = u;
    }
    if (idx < LL * CFUSE) {
        int l = idx / CFUSE, c = idx % CFUSE;
        g_bfL[idx] = (c < 64) ? 0.f : cb[l * 96 + (c - 64)];
    }
}

// ---------------- main GEMM via tf32 HMMA, fused BN-apply, persistent full-W smem ----
#define BM 64
#define ASTR 36
#define BSTR 164
#define NTILE ((NN + BM - 1) / BM)     /* 1563 */
#define GEMM_GRID 296
#define GEMM_SMEM ((HID * BSTR + BM * ASTR) * 4)   /* 93,184 B dynamic */

__global__ __launch_bounds__(256) void gemm160_mma_kernel(int l, int residual) {
    extern __shared__ unsigned smem_dyn[];
    unsigned* Wsh = smem_dyn;               // 128 x 164
    unsigned* Ash = smem_dyn + HID * BSTR;  // 64 x 36
    int t = threadIdx.x;
    if (blockIdx.x == 0 && t < HID) {       // reset stat totals for the following agg
        g_ps[t] = 0.f; g_pq[t] = 0.f;
    }
    int lane = t & 31, wid = t >> 5;
    int wm = wid >> 1;              // 0..3 : m16 group
    int wn = wid & 1;               // 0..1 : 80-col half
    int gidA = lane & 3;
    int grpA = lane >> 2;
    const unsigned* Wg = g_Wt + (size_t)l * HID * CFUSE;
    const float* bf = g_bfL + l * CFUSE;

    // load the FULL 128x160 weight once per block (5120 uint4)
    #pragma unroll
    for (int q = 0; q < 20; q++) {
        int q4 = t + q * 256;               // 0..5119
        int k = q4 / 40, c4 = (q4 % 40) << 2;
        uint4 v = *(const uint4*)(Wg + k * CFUSE + c4);
        *(uint4*)(Wsh + k * BSTR + c4) = v;
    }

    for (int tile = blockIdx.x; tile < NTILE; tile += gridDim.x) {
        int row0 = tile * BM;
        float acc[10][4];
        #pragma unroll
        for (int i = 0; i < 10; i++)
            #pragma unroll
            for (int j = 0; j < 4; j++) acc[i][j] = 0.f;

        for (int kc = 0; kc < HID; kc += 32) {
            #pragma unroll
            for (int q = 0; q < 2; q++) {
                int q4 = t + q * 256;               // 0..511
                int r = q4 >> 3, c4 = (q4 & 7) << 2;
                int gr = row0 + r;
                float4 v = make_float4(0.f, 0.f, 0.f, 0.f);
                if (gr < NN) {
                    int f = kc + c4;
                    float4 tv = *(const float4*)(g_tmp + (size_t)gr * HID + f);
                    v.x = fmaxf(fmaf(tv.x, g_aff[f],     g_aff[HID + f]),     0.f);
                    v.y = fmaxf(fmaf(tv.y, g_aff[f + 1], g_aff[HID + f + 1]), 0.f);
                    v.z = fmaxf(fmaf(tv.z, g_aff[f + 2], g_aff[HID + f + 2]), 0.f);
                    v.w = fmaxf(fmaf(tv.w, g_aff[f + 3], g_aff[HID + f + 3]), 0.f);
                    if (residual) {
                        float4 hv = *(const float4*)(g_h + (size_t)gr * HID + f);
                        v.x += hv.x; v.y += hv.y; v.z += hv.z; v.w += hv.w;
                    }
                    *(float4*)(g_h + (size_t)gr * HID + f) = v;
                }
                unsigned u0, u1, u2, u3;
                asm("cvt.rna.tf32.f32 %0, %1;" : "=r"(u0) : "f"(v.x));
                asm("cvt.rna.tf32.f32 %0, %1;" : "=r"(u1) : "f"(v.y));
                asm("cvt.rna.tf32.f32 %0, %1;" : "=r"(u2) : "f"(v.z));
                asm("cvt.rna.tf32.f32 %0, %1;" : "=r"(u3) : "f"(v.w));
                unsigned* p = Ash + r * ASTR + c4;
                p[0] = u0; p[1] = u1; p[2] = u2; p[3] = u3;
            }
            __syncthreads();

            #pragma unroll
            for (int ks = 0; ks < 4; ks++) {
                int k0 = kc + ks * 8;               // global k for Wsh
                int ka = ks * 8;                    // local k for Ash
                int arow = wm * 16 + grpA;
                unsigned a0 = Ash[arow * ASTR + ka + gidA];
                unsigned a1 = Ash[(arow + 8) * ASTR + ka + gidA];
                unsigned a2 = Ash[arow * ASTR + ka + gidA + 4];
                unsigned a3 = Ash[(arow + 8) * ASTR + ka + gidA + 4];
                #pragma unroll
                for (int tl = 0; tl < 10; tl++) {
                    int n0 = wn * 80 + tl * 8;
                    unsigned b0 = Wsh[(k0 + gidA) * BSTR + n0 + grpA];
                    unsigned b1 = Wsh[(k0 + gidA + 4) * BSTR + n0 + grpA];
                    asm volatile(
                        "mma.sync.aligned.m16n8k8.row.col.f32.tf32.tf32.f32 "
                        "{%0,%1,%2,%3}, {%4,%5,%6,%7}, {%8,%9}, {%0,%1,%2,%3};"
                        : "+f"(acc[tl][0]), "+f"(acc[tl][1]),
                          "+f"(acc[tl][2]), "+f"(acc[tl][3])
                        : "r"(a0), "r"(a1), "r"(a2), "r"(a3), "r"(b0), "r"(b1));
                }
            }
            __syncthreads();
        }

        int grow = row0 + wm * 16 + grpA;
        #pragma unroll
        for (int tl = 0; tl < 10; tl++) {
            int c = wn * 80 + tl * 8 + 2 * gidA;
            float b0 = bf[c], b1 = bf[c + 1];
            float2 v0 = make_float2(acc[tl][0] + b0, acc[tl][1] + b1);
            float2 v1 = make_float2(acc[tl][2] + b0, acc[tl][3] + b1);
            if (c < 64) {
                if (grow < NN)     *(float2*)(g_bs + (size_t)grow * 64 + c) = v0;
                if (grow + 8 < NN) *(float2*)(g_bs + (size_t)(grow + 8) * 64 + c) = v1;
            } else {
                int cc = c - 64;
                if (grow < NN)     *(float2*)(g_cb + (size_t)grow * 96 + cc) = v0;
                if (grow + 8 < NN) *(float2*)(g_cb + (size_t)(grow + 8) * 96 + cc) = v1;
            }
        }
    }
}

// ---------------- aggregation + einsum + fused BN stats: one warp per node ----------------
// Quarter-warp gather: 8 lanes per neighbor, 4 neighbors in flight per warp.
// NN % 8 == 0, grid = NN/8 exactly: every warp has a valid node.
__global__ __launch_bounds__(256) void agg_kernel(const float* __restrict__ cbias,
                                                  float* __restrict__ out) {
    __shared__ float sh[8][224];
    __shared__ int   shidx[8][32];
    __shared__ float sh_ps[8][HID];
    __shared__ float sh_pq[8][HID];
    int t = threadIdx.x;
    int w = t >> 5, lane = t & 31;
    int qid = lane >> 3, sub = lane & 7;        // lane covers floats [8*sub, 8*sub+8)
    int node = blockIdx.x * 8 + w;
    const float NEG = __int_as_float(0xff800000);
    const float4* bs4 = (const float4*)g_bs;    // row stride 16 float4

    const float4* self = bs4 + (size_t)node * 16 + 2 * sub;
    float4 s0, s1, m0, m1;
    if (qid == 0) {                              // self loop counted once
        s0 = self[0]; s1 = self[1]; m0 = s0; m1 = s1;
    } else {
        s0 = make_float4(0.f, 0.f, 0.f, 0.f); s1 = s0;
        m0 = make_float4(NEG, NEG, NEG, NEG); m1 = m0;
    }

    int beg = g_off[node];
    int dg  = g_off[node + 1] - beg;
    for (int base = 0; base < dg; base += 32) {
        int cnt = min(32, dg - base);
        if (lane < cnt) shidx[w][lane] = g_csr[beg + base + lane];
        __syncwarp();
        int np = (cnt + 3) >> 2;
        #pragma unroll 2
        for (int p = 0; p < np; p++) {
            int idx = 4 * p + qid;
            bool valid = idx < cnt;
            int nb = shidx[w][valid ? idx : 0];
            const float4* r = bs4 + (size_t)(valid ? nb : node) * 16 + 2 * sub;
            float4 x0 = r[0], x1 = r[1];
            if (valid) {
                s0.x += x0.x; s0.y += x0.y; s0.z += x0.z; s0.w += x0.w;
                s1.x += x1.x; s1.y += x1.y; s1.z += x1.z; s1.w += x1.w;
                m0.x = fmaxf(m0.x, x0.x); m0.y = fmaxf(m0.y, x0.y);
                m0.z = fmaxf(m0.z, x0.z); m0.w = fmaxf(m0.w, x0.w);
                m1.x = fmaxf(m1.x, x1.x); m1.y = fmaxf(m1.y, x1.y);
                m1.z = fmaxf(m1.z, x1.z); m1.w = fmaxf(m1.w, x1.w);
            }
        }
        __syncwarp();                            // before shidx overwrite
    }

    // butterfly merge across the 4 quarter-groups (xor 8, then 16)
    #pragma unroll
    for (int d = 8; d <= 16; d <<= 1) {
        s0.x += __shfl_xor_sync(0xffffffffu, s0.x, d);
        s0.y += __shfl_xor_sync(0xffffffffu, s0.y, d);
        s0.z += __shfl_xor_sync(0xffffffffu, s0.z, d);
        s0.w += __shfl_xor_sync(0xffffffffu, s0.w, d);
        s1.x += __shfl_xor_sync(0xffffffffu, s1.x, d);
        s1.y += __shfl_xor_sync(0xffffffffu, s1.y, d);
        s1.z += __shfl_xor_sync(0xffffffffu, s1.z, d);
        s1.w += __shfl_xor_sync(0xffffffffu, s1.w, d);
        m0.x = fmaxf(m0.x, __shfl_xor_sync(0xffffffffu, m0.x, d));
        m0.y = fmaxf(m0.y, __shfl_xor_sync(0xffffffffu, m0.y, d));
        m0.z = fmaxf(m0.z, __shfl_xor_sync(0xffffffffu, m0.z, d));
        m0.w = fmaxf(m0.w, __shfl_xor_sync(0xffffffffu, m0.w, d));
        m1.x = fmaxf(m1.x, __shfl_xor_sync(0xffffffffu, m1.x, d));
        m1.y = fmaxf(m1.y, __shfl_xor_sync(0xffffffffu, m1.y, d));
        m1.z = fmaxf(m1.z, __shfl_xor_sync(0xffffffffu, m1.z, d));
        m1.w = fmaxf(m1.w, __shfl_xor_sync(0xffffffffu, m1.w, d));
    }

    float dinv = 1.0f / g_degf[node];

    float* S = sh[w];
    if (qid == 0) {
        int c = 8 * sub;
        S[c]     = s0.x; S[c + 1] = s0.y; S[c + 2] = s0.z; S[c + 3] = s0.w;
        S[c + 4] = s1.x; S[c + 5] = s1.y; S[c + 6] = s1.z; S[c + 7] = s1.w;
        S[64 + c]     = m0.x; S[64 + c + 1] = m0.y;
        S[64 + c + 2] = m0.z; S[64 + c + 3] = m0.w;
        S[64 + c + 4] = m1.x; S[64 + c + 5] = m1.y;
        S[64 + c + 6] = m1.z; S[64 + c + 7] = m1.w;
    }
    const float* cb = g_cb + (size_t)node * 96;
    S[128 + lane] = cb[lane];
    S[160 + lane] = cb[lane + 32];
    S[192 + lane] = cb[lane + 64];
    __syncwarp();

    #pragma unroll
    for (int j = 0; j < 4; j++) {
        int c = lane + 32 * j;
        int hh = c >> 4, f = c & 15;
        const float* cp = S + 128 + hh * 12;
        float acc = cbias[c];
        #pragma unroll
        for (int b = 0; b < 4; b++) {
            float vs = S[b * 16 + f];
            float vm = S[64 + b * 16 + f];
            acc = fmaf(cp[b],     vs,        acc);
            acc = fmaf(cp[4 + b], vs * dinv, acc);
            acc = fmaf(cp[8 + b], vm,        acc);
        }
        out[(size_t)node * HID + c] = acc;
        sh_ps[w][c] = acc;                      // plain stores, no atomics
        sh_pq[w][c] = acc * acc;
    }
    __syncthreads();
    if (t < HID) {
        float ss = 0.f, qq = 0.f;
        #pragma unroll
        for (int ww = 0; ww < 8; ww++) {
            float v = sh_ps[ww][t];
            ss += v;
            qq += sh_pq[ww][t];
        }
        atomicAdd(&g_ps[t], ss);
        atomicAdd(&g_pq[t], qq);
    }
}

// ---------------- batchnorm finalize (totals path, C == HID) ----------------
__global__ void bn_finalize_tot(const float* __restrict__ gam, const float* __restrict__ bet,
                                int n) {
    int f = threadIdx.x;
    float s = g_ps[f], q = g_pq[f];
    float mean = s / (float)n;
    float var = q / (float)n - mean * mean;
    float sc = gam[f] * rsqrtf(var + EPSB);
    g_aff[f]       = sc;
    g_aff[HID + f] = bet[f] - mean * sc;
}

// ---------------- batchnorm partials path (MLP head, small n) ----------------
__global__ void bn_stats_kernel(const float* __restrict__ x, int n, int C) {
    int f = threadIdx.x;                        // blockDim.x == C
    int rpb = (n + gridDim.x - 1) / gridDim.x;
    int r0 = blockIdx.x * rpb;
    int r1 = min(n, r0 + rpb);
    float s = 0.f, q = 0.f;
    for (int r = r0; r < r1; r++) {
        float v = x[(size_t)r * C + f];
        s += v; q = fmaf(v, v, q);
    }
    g_ps[blockIdx.x * C + f] = s;
    g_pq[blockIdx.x * C + f] = q;
}

__global__ void bn_finalize_kernel(const float* __restrict__ gam, const float* __restrict__ bet,
                                   int n, int C) {
    int f = threadIdx.x;
    if (f >= C) return;
    float s = 0.f, q = 0.f;
    for (int i = 0; i < 256; i++) { s += g_ps[i * C + f]; q += g_pq[i * C + f]; }
    float mean = s / (float)n;
    float var = q / (float)n - mean * mean;
    float sc = gam[f] * rsqrtf(var + EPSB);
    g_aff[f]     = sc;
    g_aff[C + f] = bet[f] - mean * sc;
}

__global__ void bn_apply_kernel(const float* __restrict__ x, float* __restrict__ out,
                                int n, int C, int residual) {
    int idx4 = blockIdx.x * blockDim.x + threadIdx.x;
    int total4 = (n * C) >> 2;
    if (idx4 >= total4) return;
    int f = (idx4 << 2) % C;
    float4 v = ((const float4*)x)[idx4];
    float4 r;
    r.x = fmaxf(fmaf(v.x, g_aff[f],     g_aff[C + f]),     0.f);
    r.y = fmaxf(fmaf(v.y, g_aff[f + 1], g_aff[C + f + 1]), 0.f);
    r.z = fmaxf(fmaf(v.z, g_aff[f + 2], g_aff[C + f + 2]), 0.f);
    r.w = fmaxf(fmaf(v.w, g_aff[f + 3], g_aff[C + f + 3]), 0.f);
    if (residual) {
        float4 o = ((float4*)out)[idx4];
        r.x += o.x; r.y += o.y; r.z += o.z; r.w += o.w;
    }
    ((float4*)out)[idx4] = r;
}

// ---------------- global mean pool (batch is sorted) ----------------
__global__ __launch_bounds__(128) void pool_kernel() {
    int g = blockIdx.x;
    int f = threadIdx.x;
    __shared__ int lo_s, hi_s;
    if (f == 0) {
        int lo = 0, hi = NN;
        while (lo < hi) { int mid = (lo + hi) >> 1; if (g_bi[mid] < g) lo = mid + 1; else hi = mid; }
        lo_s = lo;
        int lo2 = lo, hi2 = NN;
        while (lo2 < hi2) { int mid = (lo2 + hi2) >> 1; if (g_bi[mid] < g + 1) lo2 = mid + 1; else hi2 = mid; }
        hi_s = lo2;
    }
    __syncthreads();
    int lo = lo_s, hi = hi_s;
    float s = 0.f;
    for (int r = lo; r < hi; r++) s += g_h[(size_t)r * HID + f];
    int c = hi - lo;
    float cnt = c > 0 ? (float)c : 1.0f;
    g_pool[g * HID + f] = s / cnt;
}

// ---------------- small MLP gemm ----------------
__global__ void small_gemm_kernel(const float* __restrict__ A, const float* __restrict__ W,
                                  const float* __restrict__ bias, float* __restrict__ Cm,
                                  int n, int K, int Cn) {
    extern __shared__ float Wshf[];             // K*Cn floats
    int t = threadIdx.x;                        // blockDim.x == Cn
    for (int q = t; q < K * Cn; q += Cn) Wshf[q] = W[q];
    __syncthreads();
    int row0 = blockIdx.x * 16;
    for (int i = 0; i < 16; i++) {
        int r = row0 + i;
        if (r >= n) break;
        const float* ar = A + (size_t)r * K;
        float acc = bias ? bias[t] : 0.f;
        for (int k = 0; k < K; k++) acc = fmaf(ar[k], Wshf[k * Cn + t], acc);
        Cm[(size_t)r * Cn + t] = acc;
    }
}

// ---------------- launch ----------------
extern "C" void kernel_launch(void* const* d_in, const int* in_sizes, int n_in,
                              void* d_out, int out_size) {
    const float* x       = (const float*)d_in[0];
    const float* lin1_w  = (const float*)d_in[1];
    const float* lin1_b  = (const float*)d_in[2];
    const float* bn1_g   = (const float*)d_in[3];
    const float* bn1_b   = (const float*)d_in[4];
    const float* bases_w = (const float*)d_in[5];
    const float* comb_w  = (const float*)d_in[6];
    const float* comb_b  = (const float*)d_in[7];
    const float* conv_bias = (const float*)d_in[8];
    const float* bn_g    = (const float*)d_in[9];
    const float* bn_b    = (const float*)d_in[10];
    const float* mlp_w1  = (const float*)d_in[11];
    const float* mbn1_g  = (const float*)d_in[12];
    const float* mbn1_b  = (const float*)d_in[13];
    const float* mlp_w2  = (const float*)d_in[14];
    const float* mbn2_g  = (const float*)d_in[15];
    const float* mbn2_b  = (const float*)d_in[16];
    const float* mlp_w3  = (const float*)d_in[17];
    const float* mlp_b3  = (const float*)d_in[18];
    const void*  edge_raw = d_in[19];
    const void*  batch_raw = d_in[20];
    float* out = (float*)d_out;

    float* p_h = nullptr; float* p_tmp = nullptr;
    cudaGetSymbolAddress((void**)&p_h,   g_h);
    cudaGetSymbolAddress((void**)&p_tmp, g_tmp);
    float* p_pool = nullptr; float* p_m1 = nullptr; float* p_m2 = nullptr;
    cudaGetSymbolAddress((void**)&p_pool, g_pool);
    cudaGetSymbolAddress((void**)&p_m1,   g_m1);
    cudaGetSymbolAddress((void**)&p_m2,   g_m2);

    static int attr_done = 0;
    if (!attr_done) {
        cudaFuncSetAttribute(gemm160_mma_kernel,
                             cudaFuncAttributeMaxDynamicSharedMemorySize, GEMM_SMEM);
        attr_done = 1;
    }

    const int TB = 256;
    int gridE = (EE + TB - 1) / TB;
    int gridN = (NN + TB - 1) / TB;

    // --- index normalization + CSR (reads raw edge buffer directly) ---
    detect_kernel<<<1, 256>>>((const unsigned*)edge_raw);
    prep_kernel<<<gridN, TB>>>(batch_raw);
    count_deg_kernel<<<gridE, TB>>>(edge_raw);
    scan_kernel<<<1, 1024>>>();
    scatter_kernel<<<gridE, TB>>>(edge_raw);

    // --- pack weights (also zeroes stat totals for lin1) ---
    pack_all_w_kernel<<<(LL * HID * CFUSE + TB - 1) / TB, TB>>>(bases_w, comb_w, comb_b);

    // --- input projection with fused BN stats ---
    lin1_kernel<<<NN / 16, 128>>>(x, lin1_w, lin1_b, p_tmp);
    bn_finalize_tot<<<1, HID>>>(bn1_g, bn1_b, NN);

    // --- EGConv layers ---
    for (int l = 0; l < LL; l++) {
        gemm160_mma_kernel<<<GEMM_GRID, 256, GEMM_SMEM>>>(l, l > 0 ? 1 : 0);
        agg_kernel<<<NN / 8, 256>>>(conv_bias + l * HID, p_tmp);
        bn_finalize_tot<<<1, HID>>>(bn_g + l * HID, bn_b + l * HID, NN);
    }
    // final BN apply (layer 3) -> g_h for pooling
    {
        int total4 = (NN * HID) / 4;
        bn_apply_kernel<<<(total4 + TB - 1) / TB, TB>>>(p_tmp, p_h, NN, HID, 1);
    }

    // --- pooling + MLP head ---
    pool_kernel<<<GG, HID>>>();

    small_gemm_kernel<<<(GG + 15) / 16, 64, HID * 64 * sizeof(float)>>>(p_pool, mlp_w1, nullptr, p_m1, GG, HID, 64);
    bn_stats_kernel<<<256, 64>>>(p_m1, GG, 64);
    bn_finalize_kernel<<<1, 64>>>(mbn1_g, mbn1_b, GG, 64);
    bn_apply_kernel<<<((GG * 64 / 4) + TB - 1) / TB, TB>>>(p_m1, p_m1, GG, 64, 0);

    small_gemm_kernel<<<(GG + 15) / 16, 32, 64 * 32 * sizeof(float)>>>(p_m1, mlp_w2, nullptr, p_m2, GG, 64, 32);
    bn_stats_kernel<<<256, 32>>>(p_m2, GG, 32);
    bn_finalize_kernel<<<1, 32>>>(mbn2_g, mbn2_b, GG, 32);
    bn_apply_kernel<<<((GG * 32 / 4) + TB - 1) / TB, TB>>>(p_m2, p_m2, GG, 32, 0);

    small_gemm_kernel<<<(GG + 15) / 16, 10, 32 * 10 * sizeof(float)>>>(p_m2, mlp_w3, mlp_b3, out, GG, 32, 10);
}

// round 15
// speedup vs baseline: 1.1467x; 1.1467x over previous
#include <cuda_runtime.h>
#include <cstdint>

#define NN 100000
#define EE 1600000
#define GG 1000
#define FIN 27
#define HID 128
#define LL 4
#define CFUSE 160   /* 64 bases + 96 comb */
#define EPSB 1e-5f
#define NSCAN 98    /* ceil(NN/1024) */

// ---------------- scratch (device globals; no runtime allocation) ----------------
__device__ float    g_h  [NN * HID];
__device__ float    g_tmp[NN * HID];
__device__ float    g_bs [NN * 64];            // bases (gather target, L2-resident)
__device__ float    g_cb [NN * 96];            // comb coefficients
__device__ unsigned g_Wt [LL * HID * CFUSE];   // tf32-converted fused weights
__device__ float    g_bfL[LL * CFUSE];
__device__ int      g_csr[EE];
__device__ int      g_off[NN + 1];
__device__ int      g_cur[NN];
__device__ int      g_dcnt[NN];
__device__ int      g_bi [NN];
__device__ float    g_degf[NN];
__device__ int      g_bsum[128];
__device__ int      g_boff[128];
__device__ float    g_ps [256 * HID];          // block partials (MLP) / totals (main path)
__device__ float    g_pq [256 * HID];
__device__ float    g_aff[2 * HID];
__device__ float    g_pool[GG * HID];
__device__ float    g_m1 [GG * 64];
__device__ float    g_m2 [GG * 32];
__device__ int      g_is64;

// ---------------- dtype detection ----------------
__global__ void detect_kernel(const unsigned* __restrict__ raw) {
    __shared__ int nz;
    if (threadIdx.x == 0) nz = 0;
    __syncthreads();
    int local = 0;
    for (int i = threadIdx.x; i < 2048; i += blockDim.x)
        if (raw[2 * i + 1] != 0u) local++;
    if (local) atomicAdd(&nz, local);
    __syncthreads();
    if (threadIdx.x == 0) g_is64 = (nz == 0) ? 1 : 0;
}

// batch convert + counter zeroing in one pass
__global__ void prep_kernel(const void* __restrict__ raw) {
    int n = blockIdx.x * blockDim.x + threadIdx.x;
    if (n >= NN) return;
    if (g_is64) g_bi[n] = (int)((const long long*)raw)[n];
    else        g_bi[n] = ((const int*)raw)[n];
    g_dcnt[n] = 0;
    g_cur[n]  = 0;
}

// ---------------- CSR build (reads raw edge buffer directly) ----------------
__global__ void count_deg_kernel(const void* __restrict__ raw) {
    int e = blockIdx.x * blockDim.x + threadIdx.x;
    if (e >= EE) return;
    int d = g_is64 ? (int)((const long long*)raw)[(size_t)EE + e]
                   : ((const int*)raw)[EE + e];
    atomicAdd(&g_dcnt[d], 1);
}

// ---- 3-phase scan: local block scans -> block-sum scan -> add offsets ----
__global__ __launch_bounds__(1024) void scan_local_kernel() {
    __shared__ int wsum[32];
    int tid = threadIdx.x, lane = tid & 31, wid = tid >> 5;
    int i = blockIdx.x * 1024 + tid;
    int v = (i < NN) ? g_dcnt[i] : 0;
    if (i < NN) g_degf[i] = (float)(v + 1);   // +1 self loop
    int x = v;
    #pragma unroll
    for (int s = 1; s < 32; s <<= 1) {
        int t = __shfl_up_sync(0xffffffffu, x, s);
        if (lane >= s) x += t;
    }
    if (lane == 31) wsum[wid] = x;
    __syncthreads();
    if (wid == 0) {
        int y = wsum[lane];
        #pragma unroll
        for (int s = 1; s < 32; s <<= 1) {
            int t = __shfl_up_sync(0xffffffffu, y, s);
            if (lane >= s) y += t;
        }
        wsum[lane] = y;
    }
    __syncthreads();
    int incl = x + (wid > 0 ? wsum[wid - 1] : 0);
    if (i < NN) g_off[i + 1] = incl;
    if (tid == 1023) g_bsum[blockIdx.x] = incl;
}

__global__ void scan_bsum_kernel() {   // 1 block, 128 threads: exclusive scan of block sums
    __shared__ int wsum[4];
    int tid = threadIdx.x, lane = tid & 31, wid = tid >> 5;
    int v = (tid < NSCAN) ? g_bsum[tid] : 0;
    int x = v;
    #pragma unroll
    for (int s = 1; s < 32; s <<= 1) {
        int t = __shfl_up_sync(0xffffffffu, x, s);
        if (lane >= s) x += t;
    }
    if (lane == 31) wsum[wid] = x;
    __syncthreads();
    if (tid == 0) {
        int c = 0;
        #pragma unroll
        for (int w = 0; w < 4; w++) { int t = wsum[w]; wsum[w] = c; c += t; }
    }
    __syncthreads();
    g_boff[tid] = x - v + wsum[wid];   // exclusive prefix
    if (tid == 0) g_off[0] = 0;
}

__global__ __launch_bounds__(1024) void scan_add_kernel() {
    int i = blockIdx.x * 1024 + threadIdx.x;
    if (i < NN) g_off[i + 1] += g_boff[blockIdx.x];
}

__global__ void scatter_kernel(const void* __restrict__ raw) {
    int e = blockIdx.x * blockDim.x + threadIdx.x;
    if (e >= EE) return;
    int s, d;
    if (g_is64) {
        const long long* p = (const long long*)raw;
        s = (int)p[e]; d = (int)p[(size_t)EE + e];
    } else {
        const int* p = (const int*)raw;
        s = p[e]; d = p[EE + e];
    }
    int pos = g_off[d] + atomicAdd(&g_cur[d], 1);
    g_csr[pos] = s;
}

// ---------------- lin1: x[N,27] @ W[27,128] + b, fused BN stats ----------------
__global__ __launch_bounds__(128) void lin1_kernel(const float* __restrict__ x,
                                                   const float* __restrict__ W,
                                                   const float* __restrict__ b,
                                                   float* __restrict__ out) {
    __shared__ float Wsh[FIN * HID];
    __shared__ float xsh[16 * FIN];
    int t = threadIdx.x;
    for (int q = t; q < FIN * HID; q += 128) Wsh[q] = W[q];
    int row0 = blockIdx.x * 16;
    for (int q = t; q < 16 * FIN; q += 128) {
        int r = q / FIN, c = q % FIN;
        xsh[q] = x[(row0 + r) * FIN + c];        // NN % 16 == 0
    }
    __syncthreads();
    float bias = b[t];
    float sacc = 0.f, qacc = 0.f;
    #pragma unroll 4
    for (int i = 0; i < 16; i++) {
        float acc = bias;
        #pragma unroll
        for (int k = 0; k < FIN; k++)
            acc = fmaf(xsh[i * FIN + k], Wsh[k * HID + t], acc);
        out[(size_t)(row0 + i) * HID + t] = acc;
        sacc += acc; qacc = fmaf(acc, acc, qacc);
    }
    atomicAdd(&g_ps[t], sacc);
    atomicAdd(&g_pq[t], qacc);
}

// ---------------- pack fused weight (all layers, tf32) + zero stat totals ----------------
__global__ void pack_all_w_kernel(const float* __restrict__ bw, const float* __restrict__ cw,
                                  const float* __restrict__ cb) {
    int idx = blockIdx.x * blockDim.x + threadIdx.x;
    if (blockIdx.x == 0 && threadIdx.x < HID) {
        g_ps[threadIdx.x] = 0.f;
        g_pq[threadIdx.x] = 0.f;
    }
    if (idx < LL * HID * CFUSE) {
        int l = idx / (HID * CFUSE);
        int rem = idx % (HID * CFUSE);
        int k = rem / CFUSE, c = rem % CFUSE;
        float v = (c < 64) ? bw[(size_t)l * HID * 64 + k * 64 + c]
                           : cw[(size_t)l * HID * 96 + k * 96 + (c - 64)];
        unsigned u;
        asm("cvt.rna.tf32.f32 %0, %1;" : "=r"(u) : "f"(v));
        g_Wt[idx] = u;
    }
    if (idx < LL * CFUSE) {
        int l = idx / CFUSE, c = idx % CFUSE;
        g_bfL[idx] = (c < 64) ? 0.f : cb[l * 96 + (c - 64)];
    }
}

// ---------------- main GEMM via tf32 HMMA, fused BN-apply on the A path ----------------
#define BM 64
#define BK 32
#define ASTR 36
#define BSTR 164

__global__ __launch_bounds__(256) void gemm160_mma_kernel(int l, int residual) {
    __shared__ unsigned Ash[BM * ASTR];     // 64 x 36 tf32
    __shared__ unsigned Wsh[BK * BSTR];     // 32 x 164 tf32
    int t = threadIdx.x;
    if (blockIdx.x == 0 && t < HID) {       // reset stat totals for the following agg
        g_ps[t] = 0.f; g_pq[t] = 0.f;
    }
    int lane = t & 31, wid = t >> 5;
    int wm = wid >> 1;              // 0..3 : m16 group
    int wn = wid & 1;               // 0..1 : 80-col half
    int row0 = blockIdx.x * BM;
    const unsigned* Wg = g_Wt + (size_t)l * HID * CFUSE;

    float acc[10][4];
    #pragma unroll
    for (int i = 0; i < 10; i++)
        #pragma unroll
        for (int j = 0; j < 4; j++) acc[i][j] = 0.f;

    int gidA = lane & 3;
    int grpA = lane >> 2;

    for (int kc = 0; kc < HID; kc += BK) {
        #pragma unroll
        for (int q = 0; q < 2; q++) {
            int q4 = t + q * 256;               // 0..511
            int r = q4 >> 3, c4 = (q4 & 7) << 2;
            int gr = row0 + r;
            float4 v = make_float4(0.f, 0.f, 0.f, 0.f);
            if (gr < NN) {
                int f = kc + c4;
                float4 tv = *(const float4*)(g_tmp + (size_t)gr * HID + f);
                v.x = fmaxf(fmaf(tv.x, g_aff[f],     g_aff[HID + f]),     0.f);
                v.y = fmaxf(fmaf(tv.y, g_aff[f + 1], g_aff[HID + f + 1]), 0.f);
                v.z = fmaxf(fmaf(tv.z, g_aff[f + 2], g_aff[HID + f + 2]), 0.f);
                v.w = fmaxf(fmaf(tv.w, g_aff[f + 3], g_aff[HID + f + 3]), 0.f);
                if (residual) {
                    float4 hv = *(const float4*)(g_h + (size_t)gr * HID + f);
                    v.x += hv.x; v.y += hv.y; v.z += hv.z; v.w += hv.w;
                }
                *(float4*)(g_h + (size_t)gr * HID + f) = v;
            }
            unsigned u0, u1, u2, u3;
            asm("cvt.rna.tf32.f32 %0, %1;" : "=r"(u0) : "f"(v.x));
            asm("cvt.rna.tf32.f32 %0, %1;" : "=r"(u1) : "f"(v.y));
            asm("cvt.rna.tf32.f32 %0, %1;" : "=r"(u2) : "f"(v.z));
            asm("cvt.rna.tf32.f32 %0, %1;" : "=r"(u3) : "f"(v.w));
            unsigned* p = Ash + r * ASTR + c4;
            p[0] = u0; p[1] = u1; p[2] = u2; p[3] = u3;
        }
        #pragma unroll
        for (int q = 0; q < 5; q++) {
            int q4 = t + q * 256;               // 0..1279
            int k = q4 / 40, c4 = (q4 % 40) << 2;
            uint4 v = *(const uint4*)(Wg + (kc + k) * CFUSE + c4);
            *(uint4*)(Wsh + k * BSTR + c4) = v;
        }
        __syncthreads();

        #pragma unroll
        for (int ks = 0; ks < 4; ks++) {
            int k0 = ks * 8;
            int arow = wm * 16 + grpA;
            unsigned a0 = Ash[arow * ASTR + k0 + gidA];
            unsigned a1 = Ash[(arow + 8) * ASTR + k0 + gidA];
            unsigned a2 = Ash[arow * ASTR + k0 + gidA + 4];
            unsigned a3 = Ash[(arow + 8) * ASTR + k0 + gidA + 4];
            #pragma unroll
            for (int tile = 0; tile < 10; tile++) {
                int n0 = wn * 80 + tile * 8;
                unsigned b0 = Wsh[(k0 + gidA) * BSTR + n0 + grpA];
                unsigned b1 = Wsh[(k0 + gidA + 4) * BSTR + n0 + grpA];
                asm volatile(
                    "mma.sync.aligned.m16n8k8.row.col.f32.tf32.tf32.f32 "
                    "{%0,%1,%2,%3}, {%4,%5,%6,%7}, {%8,%9}, {%0,%1,%2,%3};"
                    : "+f"(acc[tile][0]), "+f"(acc[tile][1]),
                      "+f"(acc[tile][2]), "+f"(acc[tile][3])
                    : "r"(a0), "r"(a1), "r"(a2), "r"(a3), "r"(b0), "r"(b1));
            }
        }
        __syncthreads();
    }

    const float* bf = g_bfL + l * CFUSE;
    int grow = row0 + wm * 16 + grpA;
    #pragma unroll
    for (int tile = 0; tile < 10; tile++) {
        int c = wn * 80 + tile * 8 + 2 * gidA;
        float b0 = bf[c], b1 = bf[c + 1];
        float2 v0 = make_float2(acc[tile][0] + b0, acc[tile][1] + b1);
        float2 v1 = make_float2(acc[tile][2] + b0, acc[tile][3] + b1);
        if (c < 64) {
            if (grow < NN)     *(float2*)(g_bs + (size_t)grow * 64 + c) = v0;
            if (grow + 8 < NN) *(float2*)(g_bs + (size_t)(grow + 8) * 64 + c) = v1;
        } else {
            int cc = c - 64;
            if (grow < NN)     *(float2*)(g_cb + (size_t)grow * 96 + cc) = v0;
            if (grow + 8 < NN) *(float2*)(g_cb + (size_t)(grow + 8) * 96 + cc) = v1;
        }
    }
}

// ---------------- aggregation + einsum + fused BN stats: one warp per node ----------------
// NN % 8 == 0, grid = NN/8 exactly: every warp has a valid node (needed for block syncs).
__global__ __launch_bounds__(256) void agg_kernel(const float* __restrict__ cbias,
                                                  float* __restrict__ out) {
    __shared__ float sh[8][224];
    __shared__ float sh_ps[8][HID];
    __shared__ float sh_pq[8][HID];
    int t = threadIdx.x;
    int w = t >> 5, lane = t & 31;

    int node = blockIdx.x * 8 + w;
    int half = lane >> 4, sub = lane & 15;
    const float NEG = __int_as_float(0xff800000);
    const float4* bs4 = (const float4*)g_bs;    // row stride 16 float4

    float4 sv = bs4[(size_t)node * 16 + sub];
    float4 s, m;
    if (half == 0) { s = sv; m = sv; }          // self loop on half 0 only
    else {
        s = make_float4(0.f, 0.f, 0.f, 0.f);
        m = make_float4(NEG, NEG, NEG, NEG);
    }

    int beg = g_off[node];
    int dg  = g_off[node + 1] - beg;
    for (int base = 0; base < dg; base += 32) {
        int cnt = min(32, dg - base);
        int sidx = (lane < cnt) ? g_csr[beg + base + lane] : 0;
        #pragma unroll 4
        for (int p = 0; 2 * p < cnt; p++) {
            int idx2 = 2 * p + half;
            int nb = __shfl_sync(0xffffffffu, sidx, idx2);
            bool valid = idx2 < cnt;
            float4 xv = bs4[(size_t)(valid ? nb : node) * 16 + sub];
            if (valid) {
                s.x += xv.x; s.y += xv.y; s.z += xv.z; s.w += xv.w;
                m.x = fmaxf(m.x, xv.x); m.y = fmaxf(m.y, xv.y);
                m.z = fmaxf(m.z, xv.z); m.w = fmaxf(m.w, xv.w);
            }
        }
    }
    // merge the two halves
    s.x += __shfl_xor_sync(0xffffffffu, s.x, 16);
    s.y += __shfl_xor_sync(0xffffffffu, s.y, 16);
    s.z += __shfl_xor_sync(0xffffffffu, s.z, 16);
    s.w += __shfl_xor_sync(0xffffffffu, s.w, 16);
    m.x = fmaxf(m.x, __shfl_xor_sync(0xffffffffu, m.x, 16));
    m.y = fmaxf(m.y, __shfl_xor_sync(0xffffffffu, m.y, 16));
    m.z = fmaxf(m.z, __shfl_xor_sync(0xffffffffu, m.z, 16));
    m.w = fmaxf(m.w, __shfl_xor_sync(0xffffffffu, m.w, 16));

    float dinv = 1.0f / g_degf[node];

    float* S = sh[w];
    if (half == 0) {
        int c = 4 * sub;
        S[c]     = s.x; S[c + 1] = s.y; S[c + 2] = s.z; S[c + 3] = s.w;
        S[64 + c]     = m.x; S[64 + c + 1] = m.y;
        S[64 + c + 2] = m.z; S[64 + c + 3] = m.w;
    }
    const float* cb = g_cb + (size_t)node * 96;
    S[128 + lane] = cb[lane];
    S[160 + lane] = cb[lane + 32];
    S[192 + lane] = cb[lane + 64];
    __syncwarp();

    #pragma unroll
    for (int j = 0; j < 4; j++) {
        int c = lane + 32 * j;
        int hh = c >> 4, f = c & 15;
        const float* cp = S + 128 + hh * 12;
        float acc = cbias[c];
        #pragma unroll
        for (int b = 0; b < 4; b++) {
            float vs = S[b * 16 + f];
            float vm = S[64 + b * 16 + f];
            acc = fmaf(cp[b],     vs,        acc);
            acc = fmaf(cp[4 + b], vs * dinv, acc);
            acc = fmaf(cp[8 + b], vm,        acc);
        }
        out[(size_t)node * HID + c] = acc;
        sh_ps[w][c] = acc;                      // plain stores, no atomics
        sh_pq[w][c] = acc * acc;
    }
    __syncthreads();
    if (t < HID) {
        float ss = 0.f, qq = 0.f;
        #pragma unroll
        for (int ww = 0; ww < 8; ww++) {
            ss += sh_ps[ww][t];
            qq += sh_pq[ww][t];
        }
        atomicAdd(&g_ps[t], ss);
        atomicAdd(&g_pq[t], qq);
    }
}

// ---------------- batchnorm finalize (totals path, C == HID) ----------------
__global__ void bn_finalize_tot(const float* __restrict__ gam, const float* __restrict__ bet,
                                int n) {
    int f = threadIdx.x;
    float s = g_ps[f], q = g_pq[f];
    float mean = s / (float)n;
    float var = q / (float)n - mean * mean;
    float sc = gam[f] * rsqrtf(var + EPSB);
    g_aff[f]       = sc;
    g_aff[HID + f] = bet[f] - mean * sc;
}

// ---------------- batchnorm partials path (MLP head, small n) ----------------
__global__ void bn_stats_kernel(const float* __restrict__ x, int n, int C) {
    int f = threadIdx.x;                        // blockDim.x == C
    int rpb = (n + gridDim.x - 1) / gridDim.x;
    int r0 = blockIdx.x * rpb;
    int r1 = min(n, r0 + rpb);
    float s = 0.f, q = 0.f;
    for (int r = r0; r < r1; r++) {
        float v = x[(size_t)r * C + f];
        s += v; q = fmaf(v, v, q);
    }
    g_ps[blockIdx.x * C + f] = s;
    g_pq[blockIdx.x * C + f] = q;
}

__global__ void bn_finalize_kernel(const float* __restrict__ gam, const float* __restrict__ bet,
                                   int n, int C) {
    int f = threadIdx.x;
    if (f >= C) return;
    float s = 0.f, q = 0.f;
    for (int i = 0; i < 256; i++) { s += g_ps[i * C + f]; q += g_pq[i * C + f]; }
    float mean = s / (float)n;
    float var = q / (float)n - mean * mean;
    float sc = gam[f] * rsqrtf(var + EPSB);
    g_aff[f]     = sc;
    g_aff[C + f] = bet[f] - mean * sc;
}

__global__ void bn_apply_kernel(const float* __restrict__ x, float* __restrict__ out,
                                int n, int C, int residual) {
    int idx4 = blockIdx.x * blockDim.x + threadIdx.x;
    int total4 = (n * C) >> 2;
    if (idx4 >= total4) return;
    int f = (idx4 << 2) % C;
    float4 v = ((const float4*)x)[idx4];
    float4 r;
    r.x = fmaxf(fmaf(v.x, g_aff[f],     g_aff[C + f]),     0.f);
    r.y = fmaxf(fmaf(v.y, g_aff[f + 1], g_aff[C + f + 1]), 0.f);
    r.z = fmaxf(fmaf(v.z, g_aff[f + 2], g_aff[C + f + 2]), 0.f);
    r.w = fmaxf(fmaf(v.w, g_aff[f + 3], g_aff[C + f + 3]), 0.f);
    if (residual) {
        float4 o = ((float4*)out)[idx4];
        r.x += o.x; r.y += o.y; r.z += o.z; r.w += o.w;
    }
    ((float4*)out)[idx4] = r;
}

// ---------------- global mean pool (batch is sorted) ----------------
__global__ __launch_bounds__(128) void pool_kernel() {
    int g = blockIdx.x;
    int f = threadIdx.x;
    __shared__ int lo_s, hi_s;
    if (f == 0) {
        int lo = 0, hi = NN;
        while (lo < hi) { int mid = (lo + hi) >> 1; if (g_bi[mid] < g) lo = mid + 1; else hi = mid; }
        lo_s = lo;
        int lo2 = lo, hi2 = NN;
        while (lo2 < hi2) { int mid = (lo2 + hi2) >> 1; if (g_bi[mid] < g + 1) lo2 = mid + 1; else hi2 = mid; }
        hi_s = lo2;
    }
    __syncthreads();
    int lo = lo_s, hi = hi_s;
    float s = 0.f;
    for (int r = lo; r < hi; r++) s += g_h[(size_t)r * HID + f];
    int c = hi - lo;
    float cnt = c > 0 ? (float)c : 1.0f;
    g_pool[g * HID + f] = s / cnt;
}

// ---------------- small MLP gemm ----------------
__global__ void small_gemm_kernel(const float* __restrict__ A, const float* __restrict__ W,
                                  const float* __restrict__ bias, float* __restrict__ Cm,
                                  int n, int K, int Cn) {
    extern __shared__ float Wshf[];             // K*Cn floats
    int t = threadIdx.x;                        // blockDim.x == Cn
    for (int q = t; q < K * Cn; q += Cn) Wshf[q] = W[q];
    __syncthreads();
    int row0 = blockIdx.x * 16;
    for (int i = 0; i < 16; i++) {
        int r = row0 + i;
        if (r >= n) break;
        const float* ar = A + (size_t)r * K;
        float acc = bias ? bias[t] : 0.f;
        for (int k = 0; k < K; k++) acc = fmaf(ar[k], Wshf[k * Cn + t], acc);
        Cm[(size_t)r * Cn + t] = acc;
    }
}

// ---------------- launch ----------------
extern "C" void kernel_launch(void* const* d_in, const int* in_sizes, int n_in,
                              void* d_out, int out_size) {
    const float* x       = (const float*)d_in[0];
    const float* lin1_w  = (const float*)d_in[1];
    const float* lin1_b  = (const float*)d_in[2];
    const float* bn1_g   = (const float*)d_in[3];
    const float* bn1_b   = (const float*)d_in[4];
    const float* bases_w = (const float*)d_in[5];
    const float* comb_w  = (const float*)d_in[6];
    const float* comb_b  = (const float*)d_in[7];
    const float* conv_bias = (const float*)d_in[8];
    const float* bn_g    = (const float*)d_in[9];
    const float* bn_b    = (const float*)d_in[10];
    const float* mlp_w1  = (const float*)d_in[11];
    const float* mbn1_g  = (const float*)d_in[12];
    const float* mbn1_b  = (const float*)d_in[13];
    const float* mlp_w2  = (const float*)d_in[14];
    const float* mbn2_g  = (const float*)d_in[15];
    const float* mbn2_b  = (const float*)d_in[16];
    const float* mlp_w3  = (const float*)d_in[17];
    const float* mlp_b3  = (const float*)d_in[18];
    const void*  edge_raw = d_in[19];
    const void*  batch_raw = d_in[20];
    float* out = (float*)d_out;

    float* p_h = nullptr; float* p_tmp = nullptr;
    cudaGetSymbolAddress((void**)&p_h,   g_h);
    cudaGetSymbolAddress((void**)&p_tmp, g_tmp);
    float* p_pool = nullptr; float* p_m1 = nullptr; float* p_m2 = nullptr;
    cudaGetSymbolAddress((void**)&p_pool, g_pool);
    cudaGetSymbolAddress((void**)&p_m1,   g_m1);
    cudaGetSymbolAddress((void**)&p_m2,   g_m2);

    const int TB = 256;
    int gridE = (EE + TB - 1) / TB;
    int gridN = (NN + TB - 1) / TB;

    // --- index normalization + CSR (reads raw edge buffer directly) ---
    detect_kernel<<<1, 256>>>((const unsigned*)edge_raw);
    prep_kernel<<<gridN, TB>>>(batch_raw);
    count_deg_kernel<<<gridE, TB>>>(edge_raw);
    scan_local_kernel<<<NSCAN, 1024>>>();
    scan_bsum_kernel<<<1, 128>>>();
    scan_add_kernel<<<NSCAN, 1024>>>();
    scatter_kernel<<<gridE, TB>>>(edge_raw);

    // --- pack weights (also zeroes stat totals for lin1) ---
    pack_all_w_kernel<<<(LL * HID * CFUSE + TB - 1) / TB, TB>>>(bases_w, comb_w, comb_b);

    // --- input projection with fused BN stats ---
    lin1_kernel<<<NN / 16, 128>>>(x, lin1_w, lin1_b, p_tmp);
    bn_finalize_tot<<<1, HID>>>(bn1_g, bn1_b, NN);

    // --- EGConv layers ---
    for (int l = 0; l < LL; l++) {
        gemm160_mma_kernel<<<(NN + BM - 1) / BM, 256>>>(l, l > 0 ? 1 : 0);
        agg_kernel<<<NN / 8, 256>>>(conv_bias + l * HID, p_tmp);
        bn_finalize_tot<<<1, HID>>>(bn_g + l * HID, bn_b + l * HID, NN);
    }
    // final BN apply (layer 3) -> g_h for pooling
    {
        int total4 = (NN * HID) / 4;
        bn_apply_kernel<<<(total4 + TB - 1) / TB, TB>>>(p_tmp, p_h, NN, HID, 1);
    }

    // --- pooling + MLP head ---
    pool_kernel<<<GG, HID>>>();

    small_gemm_kernel<<<(GG + 15) / 16, 64, HID * 64 * sizeof(float)>>>(p_pool, mlp_w1, nullptr, p_m1, GG, HID, 64);
    bn_stats_kernel<<<256, 64>>>(p_m1, GG, 64);
    bn_finalize_kernel<<<1, 64>>>(mbn1_g, mbn1_b, GG, 64);
    bn_apply_kernel<<<((GG * 64 / 4) + TB - 1) / TB, TB>>>(p_m1, p_m1, GG, 64, 0);

    small_gemm_kernel<<<(GG + 15) / 16, 32, 64 * 32 * sizeof(float)>>>(p_m1, mlp_w2, nullptr, p_m2, GG, 64, 32);
    bn_stats_kernel<<<256, 32>>>(p_m2, GG, 32);
    bn_finalize_kernel<<<1, 32>>>(mbn2_g, mbn2_b, GG, 32);
    bn_apply_kernel<<<((GG * 32 / 4) + TB - 1) / TB, TB>>>(p_m2, p_m2, GG, 32, 0);

    small_gemm_kernel<<<(GG + 15) / 16, 10, 32 * 10 * sizeof(float)>>>(p_m2, mlp_w3, mlp_b3, out, GG, 32, 10);
}

// round 16
// speedup vs baseline: 1.1905x; 1.0382x over previous
#include <cuda_runtime.h>
#include <cstdint>

#define NN 100000
#define EE 1600000
#define GG 1000
#define FIN 27
#define HID 128
#define LL 4
#define CFUSE 160   /* 64 bases + 96 comb */
#define EPSB 1e-5f
#define NSCAN 98    /* ceil(NN/1024) */

// ---------------- scratch (device globals; no runtime allocation) ----------------
__device__ float    g_h  [NN * HID];
__device__ float    g_tmp[NN * HID];
__device__ float    g_bs [NN * 64];            // bases (gather target, L2-resident)
__device__ float    g_cb [NN * 96];            // comb coefficients
__device__ unsigned g_Wt [LL * HID * CFUSE];   // tf32-converted fused weights
__device__ float    g_bfL[LL * CFUSE];
__device__ int      g_csr[EE];
__device__ int      g_off[NN + 1];
__device__ int      g_cur[NN];
__device__ int      g_dcnt[NN];
__device__ int      g_bi [NN];
__device__ float    g_degf[NN];
__device__ int      g_bsum[128];
__device__ int      g_boff[128];
__device__ float    g_ps [HID];                // stat totals (zeroed by finalize after read)
__device__ float    g_pq [HID];
__device__ float    g_aff[2 * HID];
__device__ float    g_pool[GG * HID];
__device__ float    g_m1 [GG * 64];
__device__ float    g_m2 [GG * 32];
__device__ int      g_is64;

// ---------------- dtype detection ----------------
__global__ void detect_kernel(const unsigned* __restrict__ raw) {
    __shared__ int nz;
    if (threadIdx.x == 0) nz = 0;
    __syncthreads();
    int local = 0;
    for (int i = threadIdx.x; i < 2048; i += blockDim.x)
        if (raw[2 * i + 1] != 0u) local++;
    if (local) atomicAdd(&nz, local);
    __syncthreads();
    if (threadIdx.x == 0) g_is64 = (nz == 0) ? 1 : 0;
}

// batch convert + counter zeroing in one pass
__global__ void prep_kernel(const void* __restrict__ raw) {
    int n = blockIdx.x * blockDim.x + threadIdx.x;
    if (n >= NN) return;
    if (g_is64) g_bi[n] = (int)((const long long*)raw)[n];
    else        g_bi[n] = ((const int*)raw)[n];
    g_dcnt[n] = 0;
    g_cur[n]  = 0;
}

// ---------------- CSR build (reads raw edge buffer directly) ----------------
__global__ void count_deg_kernel(const void* __restrict__ raw) {
    int e = blockIdx.x * blockDim.x + threadIdx.x;
    if (e >= EE) return;
    int d = g_is64 ? (int)((const long long*)raw)[(size_t)EE + e]
                   : ((const int*)raw)[EE + e];
    atomicAdd(&g_dcnt[d], 1);
}

// ---- 3-phase scan: local block scans -> block-sum scan -> add offsets ----
__global__ __launch_bounds__(1024) void scan_local_kernel() {
    __shared__ int wsum[32];
    int tid = threadIdx.x, lane = tid & 31, wid = tid >> 5;
    int i = blockIdx.x * 1024 + tid;
    int v = (i < NN) ? g_dcnt[i] : 0;
    if (i < NN) g_degf[i] = (float)(v + 1);   // +1 self loop
    int x = v;
    #pragma unroll
    for (int s = 1; s < 32; s <<= 1) {
        int t = __shfl_up_sync(0xffffffffu, x, s);
        if (lane >= s) x += t;
    }
    if (lane == 31) wsum[wid] = x;
    __syncthreads();
    if (wid == 0) {
        int y = wsum[lane];
        #pragma unroll
        for (int s = 1; s < 32; s <<= 1) {
            int t = __shfl_up_sync(0xffffffffu, y, s);
            if (lane >= s) y += t;
        }
        wsum[lane] = y;
    }
    __syncthreads();
    int incl = x + (wid > 0 ? wsum[wid - 1] : 0);
    if (i < NN) g_off[i + 1] = incl;
    if (tid == 1023) g_bsum[blockIdx.x] = incl;
}

__global__ void scan_bsum_kernel() {   // 1 block, 128 threads: exclusive scan of block sums
    __shared__ int wsum[4];
    int tid = threadIdx.x, lane = tid & 31, wid = tid >> 5;
    int v = (tid < NSCAN) ? g_bsum[tid] : 0;
    int x = v;
    #pragma unroll
    for (int s = 1; s < 32; s <<= 1) {
        int t = __shfl_up_sync(0xffffffffu, x, s);
        if (lane >= s) x += t;
    }
    if (lane == 31) wsum[wid] = x;
    __syncthreads();
    if (tid == 0) {
        int c = 0;
        #pragma unroll
        for (int w = 0; w < 4; w++) { int t = wsum[w]; wsum[w] = c; c += t; }
    }
    __syncthreads();
    g_boff[tid] = x - v + wsum[wid];   // exclusive prefix
    if (tid == 0) g_off[0] = 0;
}

__global__ __launch_bounds__(1024) void scan_add_kernel() {
    int i = blockIdx.x * 1024 + threadIdx.x;
    if (i < NN) g_off[i + 1] += g_boff[blockIdx.x];
}

__global__ void scatter_kernel(const void* __restrict__ raw) {
    int e = blockIdx.x * blockDim.x + threadIdx.x;
    if (e >= EE) return;
    int s, d;
    if (g_is64) {
        const long long* p = (const long long*)raw;
        s = (int)p[e]; d = (int)p[(size_t)EE + e];
    } else {
        const int* p = (const int*)raw;
        s = p[e]; d = p[EE + e];
    }
    int pos = g_off[d] + atomicAdd(&g_cur[d], 1);
    g_csr[pos] = s;
}

// ---------------- lin1: x[N,27] @ W[27,128] + b, fused BN stats ----------------
__global__ __launch_bounds__(128) void lin1_kernel(const float* __restrict__ x,
                                                   const float* __restrict__ W,
                                                   const float* __restrict__ b,
                                                   float* __restrict__ out) {
    __shared__ float Wsh[FIN * HID];
    __shared__ float xsh[16 * FIN];
    int t = threadIdx.x;
    for (int q = t; q < FIN * HID; q += 128) Wsh[q] = W[q];
    int row0 = blockIdx.x * 16;
    for (int q = t; q < 16 * FIN; q += 128) {
        int r = q / FIN, c = q % FIN;
        xsh[q] = x[(row0 + r) * FIN + c];        // NN % 16 == 0
    }
    __syncthreads();
    float bias = b[t];
    float sacc = 0.f, qacc = 0.f;
    #pragma unroll 4
    for (int i = 0; i < 16; i++) {
        float acc = bias;
        #pragma unroll
        for (int k = 0; k < FIN; k++)
            acc = fmaf(xsh[i * FIN + k], Wsh[k * HID + t], acc);
        __stcs(out + (size_t)(row0 + i) * HID + t, acc);
        sacc += acc; qacc = fmaf(acc, acc, qacc);
    }
    atomicAdd(&g_ps[t], sacc);
    atomicAdd(&g_pq[t], qacc);
}

// ---------------- pack fused weight (all layers, tf32) + zero stat totals ----------------
__global__ void pack_all_w_kernel(const float* __restrict__ bw, const float* __restrict__ cw,
                                  const float* __restrict__ cb) {
    int idx = blockIdx.x * blockDim.x + threadIdx.x;
    if (blockIdx.x == 0 && threadIdx.x < HID) {
        g_ps[threadIdx.x] = 0.f;
        g_pq[threadIdx.x] = 0.f;
    }
    if (idx < LL * HID * CFUSE) {
        int l = idx / (HID * CFUSE);
        int rem = idx % (HID * CFUSE);
        int k = rem / CFUSE, c = rem % CFUSE;
        float v = (c < 64) ? bw[(size_t)l * HID * 64 + k * 64 + c]
                           : cw[(size_t)l * HID * 96 + k * 96 + (c - 64)];
        unsigned u;
        asm("cvt.rna.tf32.f32 %0, %1;" : "=r"(u) : "f"(v));
        g_Wt[idx] = u;
    }
    if (idx < LL * CFUSE) {
        int l = idx / CFUSE, c = idx % CFUSE;
        g_bfL[idx] = (c < 64) ? 0.f : cb[l * 96 + (c - 64)];
    }
}

// ---------------- main GEMM via tf32 HMMA, fused BN-apply on the A path ----------------
#define BM 64
#define BK 32
#define ASTR 36
#define BSTR 164

__global__ __launch_bounds__(256) void gemm160_mma_kernel(int l, int residual) {
    __shared__ unsigned Ash[BM * ASTR];     // 64 x 36 tf32
    __shared__ unsigned Wsh[BK * BSTR];     // 32 x 164 tf32
    int t = threadIdx.x;
    int lane = t & 31, wid = t >> 5;
    int wm = wid >> 1;              // 0..3 : m16 group
    int wn = wid & 1;               // 0..1 : 80-col half
    int row0 = blockIdx.x * BM;
    const unsigned* Wg = g_Wt + (size_t)l * HID * CFUSE;

    float acc[10][4];
    #pragma unroll
    for (int i = 0; i < 10; i++)
        #pragma unroll
        for (int j = 0; j < 4; j++) acc[i][j] = 0.f;

    int gidA = lane & 3;
    int grpA = lane >> 2;

    for (int kc = 0; kc < HID; kc += BK) {
        #pragma unroll
        for (int q = 0; q < 2; q++) {
            int q4 = t + q * 256;               // 0..511
            int r = q4 >> 3, c4 = (q4 & 7) << 2;
            int gr = row0 + r;
            float4 v = make_float4(0.f, 0.f, 0.f, 0.f);
            if (gr < NN) {
                int f = kc + c4;
                float4 tv = __ldcs((const float4*)(g_tmp + (size_t)gr * HID + f));
                v.x = fmaxf(fmaf(tv.x, g_aff[f],     g_aff[HID + f]),     0.f);
                v.y = fmaxf(fmaf(tv.y, g_aff[f + 1], g_aff[HID + f + 1]), 0.f);
                v.z = fmaxf(fmaf(tv.z, g_aff[f + 2], g_aff[HID + f + 2]), 0.f);
                v.w = fmaxf(fmaf(tv.w, g_aff[f + 3], g_aff[HID + f + 3]), 0.f);
                if (residual) {
                    float4 hv = __ldcs((const float4*)(g_h + (size_t)gr * HID + f));
                    v.x += hv.x; v.y += hv.y; v.z += hv.z; v.w += hv.w;
                }
                __stcs((float4*)(g_h + (size_t)gr * HID + f), v);
            }
            unsigned u0, u1, u2, u3;
            asm("cvt.rna.tf32.f32 %0, %1;" : "=r"(u0) : "f"(v.x));
            asm("cvt.rna.tf32.f32 %0, %1;" : "=r"(u1) : "f"(v.y));
            asm("cvt.rna.tf32.f32 %0, %1;" : "=r"(u2) : "f"(v.z));
            asm("cvt.rna.tf32.f32 %0, %1;" : "=r"(u3) : "f"(v.w));
            unsigned* p = Ash + r * ASTR + c4;
            p[0] = u0; p[1] = u1; p[2] = u2; p[3] = u3;
        }
        #pragma unroll
        for (int q = 0; q < 5; q++) {
            int q4 = t + q * 256;               // 0..1279
            int k = q4 / 40, c4 = (q4 % 40) << 2;
            uint4 v = *(const uint4*)(Wg + (kc + k) * CFUSE + c4);
            *(uint4*)(Wsh + k * BSTR + c4) = v;
        }
        __syncthreads();

        #pragma unroll
        for (int ks = 0; ks < 4; ks++) {
            int k0 = ks * 8;
            int arow = wm * 16 + grpA;
            unsigned a0 = Ash[arow * ASTR + k0 + gidA];
            unsigned a1 = Ash[(arow + 8) * ASTR + k0 + gidA];
            unsigned a2 = Ash[arow * ASTR + k0 + gidA + 4];
            unsigned a3 = Ash[(arow + 8) * ASTR + k0 + gidA + 4];
            #pragma unroll
            for (int tile = 0; tile < 10; tile++) {
                int n0 = wn * 80 + tile * 8;
                unsigned b0 = Wsh[(k0 + gidA) * BSTR + n0 + grpA];
                unsigned b1 = Wsh[(k0 + gidA + 4) * BSTR + n0 + grpA];
                asm volatile(
                    "mma.sync.aligned.m16n8k8.row.col.f32.tf32.tf32.f32 "
                    "{%0,%1,%2,%3}, {%4,%5,%6,%7}, {%8,%9}, {%0,%1,%2,%3};"
                    : "+f"(acc[tile][0]), "+f"(acc[tile][1]),
                      "+f"(acc[tile][2]), "+f"(acc[tile][3])
                    : "r"(a0), "r"(a1), "r"(a2), "r"(a3), "r"(b0), "r"(b1));
            }
        }
        __syncthreads();
    }

    const float* bf = g_bfL + l * CFUSE;
    int grow = row0 + wm * 16 + grpA;
    #pragma unroll
    for (int tile = 0; tile < 10; tile++) {
        int c = wn * 80 + tile * 8 + 2 * gidA;
        float b0 = bf[c], b1 = bf[c + 1];
        float2 v0 = make_float2(acc[tile][0] + b0, acc[tile][1] + b1);
        float2 v1 = make_float2(acc[tile][2] + b0, acc[tile][3] + b1);
        if (c < 64) {
            if (grow < NN)     *(float2*)(g_bs + (size_t)grow * 64 + c) = v0;
            if (grow + 8 < NN) *(float2*)(g_bs + (size_t)(grow + 8) * 64 + c) = v1;
        } else {
            int cc = c - 64;
            if (grow < NN)     __stcs((float2*)(g_cb + (size_t)grow * 96 + cc), v0);
            if (grow + 8 < NN) __stcs((float2*)(g_cb + (size_t)(grow + 8) * 96 + cc), v1);
        }
    }
}

// ---------------- aggregation + einsum + fused BN stats: one warp per node ----------------
// NN % 8 == 0, grid = NN/8 exactly: every warp has a valid node (needed for block syncs).
__global__ __launch_bounds__(256) void agg_kernel(const float* __restrict__ cbias,
                                                  float* __restrict__ out) {
    __shared__ float sh[8][224];
    __shared__ float sh_ps[8][HID];
    __shared__ float sh_pq[8][HID];
    int t = threadIdx.x;
    int w = t >> 5, lane = t & 31;

    int node = blockIdx.x * 8 + w;
    int half = lane >> 4, sub = lane & 15;
    const float NEG = __int_as_float(0xff800000);
    const float4* bs4 = (const float4*)g_bs;    // row stride 16 float4

    float4 sv = bs4[(size_t)node * 16 + sub];
    float4 s, m;
    if (half == 0) { s = sv; m = sv; }          // self loop on half 0 only
    else {
        s = make_float4(0.f, 0.f, 0.f, 0.f);
        m = make_float4(NEG, NEG, NEG, NEG);
    }

    int beg = g_off[node];
    int dg  = g_off[node + 1] - beg;
    for (int base = 0; base < dg; base += 32) {
        int cnt = min(32, dg - base);
        int sidx = (lane < cnt) ? g_csr[beg + base + lane] : 0;
        #pragma unroll 4
        for (int p = 0; 2 * p < cnt; p++) {
            int idx2 = 2 * p + half;
            int nb = __shfl_sync(0xffffffffu, sidx, idx2);
            bool valid = idx2 < cnt;
            float4 xv = bs4[(size_t)(valid ? nb : node) * 16 + sub];
            if (valid) {
                s.x += xv.x; s.y += xv.y; s.z += xv.z; s.w += xv.w;
                m.x = fmaxf(m.x, xv.x); m.y = fmaxf(m.y, xv.y);
                m.z = fmaxf(m.z, xv.z); m.w = fmaxf(m.w, xv.w);
            }
        }
    }
    // merge the two halves
    s.x += __shfl_xor_sync(0xffffffffu, s.x, 16);
    s.y += __shfl_xor_sync(0xffffffffu, s.y, 16);
    s.z += __shfl_xor_sync(0xffffffffu, s.z, 16);
    s.w += __shfl_xor_sync(0xffffffffu, s.w, 16);
    m.x = fmaxf(m.x, __shfl_xor_sync(0xffffffffu, m.x, 16));
    m.y = fmaxf(m.y, __shfl_xor_sync(0xffffffffu, m.y, 16));
    m.z = fmaxf(m.z, __shfl_xor_sync(0xffffffffu, m.z, 16));
    m.w = fmaxf(m.w, __shfl_xor_sync(0xffffffffu, m.w, 16));

    float dinv = 1.0f / g_degf[node];

    float* S = sh[w];
    if (half == 0) {
        int c = 4 * sub;
        S[c]     = s.x; S[c + 1] = s.y; S[c + 2] = s.z; S[c + 3] = s.w;
        S[64 + c]     = m.x; S[64 + c + 1] = m.y;
        S[64 + c + 2] = m.z; S[64 + c + 3] = m.w;
    }
    const float* cb = g_cb + (size_t)node * 96;
    S[128 + lane] = __ldcs(cb + lane);
    S[160 + lane] = __ldcs(cb + lane + 32);
    S[192 + lane] = __ldcs(cb + lane + 64);
    __syncwarp();

    #pragma unroll
    for (int j = 0; j < 4; j++) {
        int c = lane + 32 * j;
        int hh = c >> 4, f = c & 15;
        const float* cp = S + 128 + hh * 12;
        float acc = cbias[c];
        #pragma unroll
        for (int b = 0; b < 4; b++) {
            float vs = S[b * 16 + f];
            float vm = S[64 + b * 16 + f];
            acc = fmaf(cp[b],     vs,        acc);
            acc = fmaf(cp[4 + b], vs * dinv, acc);
            acc = fmaf(cp[8 + b], vm,        acc);
        }
        __stcs(out + (size_t)node * HID + c, acc);
        sh_ps[w][c] = acc;                      // plain stores, no atomics
        sh_pq[w][c] = acc * acc;
    }
    __syncthreads();
    if (t < HID) {
        float ss = 0.f, qq = 0.f;
        #pragma unroll
        for (int ww = 0; ww < 8; ww++) {
            ss += sh_ps[ww][t];
            qq += sh_pq[ww][t];
        }
        atomicAdd(&g_ps[t], ss);
        atomicAdd(&g_pq[t], qq);
    }
}

// ------- batchnorm finalize from totals: reads g_ps/g_pq then ZEROES them -------
__global__ void bn_finalize_tot(const float* __restrict__ gam, const float* __restrict__ bet,
                                int n, int C) {
    int f = threadIdx.x;
    if (f >= C) return;
    float s = g_ps[f], q = g_pq[f];
    g_ps[f] = 0.f; g_pq[f] = 0.f;               // ready for next stats user
    float mean = s / (float)n;
    float var = q / (float)n - mean * mean;
    float sc = gam[f] * rsqrtf(var + EPSB);
    g_aff[f]     = sc;
    g_aff[C + f] = bet[f] - mean * sc;
}

// ---------------- global mean pool with fused final BN apply (batch sorted) ----------------
__global__ __launch_bounds__(128) void pool_kernel() {
    int g = blockIdx.x;
    int f = threadIdx.x;
    __shared__ int lo_s, hi_s;
    if (f == 0) {
        int lo = 0, hi = NN;
        while (lo < hi) { int mid = (lo + hi) >> 1; if (g_bi[mid] < g) lo = mid + 1; else hi = mid; }
        lo_s = lo;
        int lo2 = lo, hi2 = NN;
        while (lo2 < hi2) { int mid = (lo2 + hi2) >> 1; if (g_bi[mid] < g + 1) lo2 = mid + 1; else hi2 = mid; }
        hi_s = lo2;
    }
    __syncthreads();
    int lo = lo_s, hi = hi_s;
    float sc = g_aff[f], sb = g_aff[HID + f];
    float s = 0.f;
    for (int r = lo; r < hi; r++) {
        float tv = __ldcs(g_tmp + (size_t)r * HID + f);
        float hv = __ldcs(g_h   + (size_t)r * HID + f);
        s += hv + fmaxf(fmaf(tv, sc, sb), 0.f);
    }
    int c = hi - lo;
    float cnt = c > 0 ? (float)c : 1.0f;
    g_pool[g * HID + f] = s / cnt;
}

// ---------------- MLP gemms (fused stats / fused BN apply on A) ----------------
// out = A @ W ; accumulate BN stats of output
__global__ void sg_stats_kernel(const float* __restrict__ A, const float* __restrict__ W,
                                float* __restrict__ Cm, int n, int K, int Cn) {
    extern __shared__ float Wshf[];              // K*Cn floats
    int t = threadIdx.x;                         // blockDim.x == Cn
    for (int q = t; q < K * Cn; q += Cn) Wshf[q] = W[q];
    __syncthreads();
    int row0 = blockIdx.x * 16;
    float sacc = 0.f, qacc = 0.f;
    for (int i = 0; i < 16; i++) {
        int r = row0 + i;
        if (r >= n) break;
        const float* ar = A + (size_t)r * K;
        float acc = 0.f;
        for (int k = 0; k < K; k++) acc = fmaf(ar[k], Wshf[k * Cn + t], acc);
        Cm[(size_t)r * Cn + t] = acc;
        sacc += acc; qacc = fmaf(acc, acc, qacc);
    }
    atomicAdd(&g_ps[t], sacc);
    atomicAdd(&g_pq[t], qacc);
}

// out = relu(bn(A)) @ W via affine on A-read; accumulate stats of output
__global__ void sg_apply_stats_kernel(const float* __restrict__ A, const float* __restrict__ W,
                                      float* __restrict__ Cm, int n, int K, int Cn) {
    extern __shared__ float smf[];               // K*Cn weights + 2K affine
    float* Wshf = smf;
    float* aff  = smf + K * Cn;
    int t = threadIdx.x;
    for (int q = t; q < K * Cn; q += Cn) Wshf[q] = W[q];
    for (int q = t; q < K; q += Cn) { aff[q] = g_aff[q]; aff[K + q] = g_aff[K + q]; }
    __syncthreads();
    int row0 = blockIdx.x * 16;
    float sacc = 0.f, qacc = 0.f;
    for (int i = 0; i < 16; i++) {
        int r = row0 + i;
        if (r >= n) break;
        const float* ar = A + (size_t)r * K;
        float acc = 0.f;
        for (int k = 0; k < K; k++) {
            float av = fmaxf(fmaf(ar[k], aff[k], aff[K + k]), 0.f);
            acc = fmaf(av, Wshf[k * Cn + t], acc);
        }
        Cm[(size_t)r * Cn + t] = acc;
        sacc += acc; qacc = fmaf(acc, acc, qacc);
    }
    atomicAdd(&g_ps[t], sacc);
    atomicAdd(&g_pq[t], qacc);
}

// out = relu(bn(A)) @ W + bias  (final head, no stats)
__global__ void sg_apply_final_kernel(const float* __restrict__ A, const float* __restrict__ W,
                                      const float* __restrict__ bias, float* __restrict__ Cm,
                                      int n, int K, int Cn) {
    extern __shared__ float smf[];
    float* Wshf = smf;
    float* aff  = smf + K * Cn;
    int t = threadIdx.x;
    for (int q = t; q < K * Cn; q += Cn) Wshf[q] = W[q];
    for (int q = t; q < K; q += Cn) { aff[q] = g_aff[q]; aff[K + q] = g_aff[K + q]; }
    __syncthreads();
    int row0 = blockIdx.x * 16;
    for (int i = 0; i < 16; i++) {
        int r = row0 + i;
        if (r >= n) break;
        const float* ar = A + (size_t)r * K;
        float acc = bias[t];
        for (int k = 0; k < K; k++) {
            float av = fmaxf(fmaf(ar[k], aff[k], aff[K + k]), 0.f);
            acc = fmaf(av, Wshf[k * Cn + t], acc);
        }
        Cm[(size_t)r * Cn + t] = acc;
    }
}

// ---------------- launch ----------------
extern "C" void kernel_launch(void* const* d_in, const int* in_sizes, int n_in,
                              void* d_out, int out_size) {
    const float* x       = (const float*)d_in[0];
    const float* lin1_w  = (const float*)d_in[1];
    const float* lin1_b  = (const float*)d_in[2];
    const float* bn1_g   = (const float*)d_in[3];
    const float* bn1_b   = (const float*)d_in[4];
    const float* bases_w = (const float*)d_in[5];
    const float* comb_w  = (const float*)d_in[6];
    const float* comb_b  = (const float*)d_in[7];
    const float* conv_bias = (const float*)d_in[8];
    const float* bn_g    = (const float*)d_in[9];
    const float* bn_b    = (const float*)d_in[10];
    const float* mlp_w1  = (const float*)d_in[11];
    const float* mbn1_g  = (const float*)d_in[12];
    const float* mbn1_b  = (const float*)d_in[13];
    const float* mlp_w2  = (const float*)d_in[14];
    const float* mbn2_g  = (const float*)d_in[15];
    const float* mbn2_b  = (const float*)d_in[16];
    const float* mlp_w3  = (const float*)d_in[17];
    const float* mlp_b3  = (const float*)d_in[18];
    const void*  edge_raw = d_in[19];
    const void*  batch_raw = d_in[20];
    float* out = (float*)d_out;

    float* p_tmp = nullptr;
    cudaGetSymbolAddress((void**)&p_tmp, g_tmp);
    float* p_pool = nullptr; float* p_m1 = nullptr; float* p_m2 = nullptr;
    cudaGetSymbolAddress((void**)&p_pool, g_pool);
    cudaGetSymbolAddress((void**)&p_m1,   g_m1);
    cudaGetSymbolAddress((void**)&p_m2,   g_m2);

    const int TB = 256;
    int gridE = (EE + TB - 1) / TB;
    int gridN = (NN + TB - 1) / TB;

    // --- index normalization + CSR (reads raw edge buffer directly) ---
    detect_kernel<<<1, 256>>>((const unsigned*)edge_raw);
    prep_kernel<<<gridN, TB>>>(batch_raw);
    count_deg_kernel<<<gridE, TB>>>(edge_raw);
    scan_local_kernel<<<NSCAN, 1024>>>();
    scan_bsum_kernel<<<1, 128>>>();
    scan_add_kernel<<<NSCAN, 1024>>>();
    scatter_kernel<<<gridE, TB>>>(edge_raw);

    // --- pack weights (also zeroes stat totals for lin1) ---
    pack_all_w_kernel<<<(LL * HID * CFUSE + TB - 1) / TB, TB>>>(bases_w, comb_w, comb_b);

    // --- input projection with fused BN stats ---
    lin1_kernel<<<NN / 16, 128>>>(x, lin1_w, lin1_b, p_tmp);
    bn_finalize_tot<<<1, HID>>>(bn1_g, bn1_b, NN, HID);

    // --- EGConv layers: gemm(l) fuses BN-apply of the PREVIOUS stage;
    //     agg fuses BN stats; finalize zeroes totals after read ---
    for (int l = 0; l < LL; l++) {
        gemm160_mma_kernel<<<(NN + BM - 1) / BM, 256>>>(l, l > 0 ? 1 : 0);
        agg_kernel<<<NN / 8, 256>>>(conv_bias + l * HID, p_tmp);
        bn_finalize_tot<<<1, HID>>>(bn_g + l * HID, bn_b + l * HID, NN, HID);
    }

    // --- pooling with fused final BN apply + MLP head ---
    pool_kernel<<<GG, HID>>>();

    sg_stats_kernel<<<(GG + 15) / 16, 64, HID * 64 * sizeof(float)>>>(p_pool, mlp_w1, p_m1, GG, HID, 64);
    bn_finalize_tot<<<1, 64>>>(mbn1_g, mbn1_b, GG, 64);
    sg_apply_stats_kernel<<<(GG + 15) / 16, 32, (64 * 32 + 2 * 64) * sizeof(float)>>>(p_m1, mlp_w2, p_m2, GG, 64, 32);
    bn_finalize_tot<<<1, 32>>>(mbn2_g, mbn2_b, GG, 32);
    sg_apply_final_kernel<<<(GG + 15) / 16, 10, (32 * 10 + 2 * 32) * sizeof(float)>>>(p_m2, mlp_w3, mlp_b3, out, GG, 32, 10);
}